// round 1
// baseline (speedup 1.0000x reference)
#include <cuda_runtime.h>

#define BATCH 64

// ------------------------- scratch (no allocs allowed) -------------------------
__device__ float g_bufA[BATCH*32*160*160];   // conv1 out; later region-conv out
__device__ float g_bufB[BATCH*32*160*160];   // normalized+PReLU
__device__ float g_pool[BATCH*32*80*80];
__device__ float g_c4[BATCH*16*73*73];
__device__ float g_c5[BATCH*16*33*33];
__device__ float g_c6[BATCH*16*28*28];
__device__ float g_c7[BATCH*16*24*24];
__device__ float g_c8[BATCH*16*8*8];

__device__ float g_wT1[363*32];
__device__ float g_wTr[288*32];
__device__ float g_wT4[2048*16];
__device__ float g_wT5[1024*16];
__device__ float g_wT6[576*16];
__device__ float g_wT7[400*16];
__device__ float g_wT8[144*16];
__device__ float g_wTfc[1024*512];

__device__ float g_scale[512];   // [region(16)][channel(32)]
__device__ float g_shift[512];

// ------------------------- weight transpose: [O][R] -> [R][O] -------------------------
#define DEFINE_TRANS(NAME, OC, R, DST)                                        \
__global__ void NAME(const float* __restrict__ w) {                           \
    int e = blockIdx.x * blockDim.x + threadIdx.x;                            \
    if (e < (OC)*(R)) {                                                       \
        int oc = e / (R);                                                     \
        int r  = e - oc * (R);                                                \
        DST[r*(OC) + oc] = w[e];                                              \
    }                                                                         \
}

DEFINE_TRANS(t_w1,  32,  363, g_wT1)
DEFINE_TRANS(t_wr,  32,  288, g_wTr)
DEFINE_TRANS(t_w4,  16, 2048, g_wT4)
DEFINE_TRANS(t_w5,  16, 1024, g_wT5)
DEFINE_TRANS(t_w6,  16,  576, g_wT6)
DEFINE_TRANS(t_w7,  16,  400, g_wT7)
DEFINE_TRANS(t_w8,  16,  144, g_wT8)
DEFINE_TRANS(t_wfc, 512, 1024, g_wTfc)

// ------------------------- conv1: 3->32, 11x11, 170->160, no pad -------------------------
// One thread computes 2 output pixels (x, x+80) for all 32 channels.
__global__ void __launch_bounds__(128) conv1_kernel(const float* __restrict__ x,
                                                    const float* __restrict__ bias) {
    int t = blockIdx.x * 128 + threadIdx.x;
    if (t >= BATCH * 160 * 80) return;
    int xo = t % 80;
    int yo = (t / 80) % 160;
    int b  = t / (80 * 160);

    float a0[32], a1[32];
#pragma unroll
    for (int j = 0; j < 32; j++) { float bv = __ldg(bias + j); a0[j] = bv; a1[j] = bv; }

    for (int ic = 0; ic < 3; ic++) {
        const float* inp = x + ((b*3 + ic)*170 + yo)*170 + xo;
#pragma unroll 1
        for (int ky = 0; ky < 11; ky++) {
            const float* row = inp + ky * 170;
            const float4* wrow = (const float4*)(g_wT1 + (ic*121 + ky*11)*32);
#pragma unroll
            for (int kx = 0; kx < 11; kx++) {
                float v0 = __ldg(row + kx);
                float v1 = __ldg(row + 80 + kx);
#pragma unroll
                for (int j = 0; j < 8; j++) {
                    float4 w4 = __ldg(wrow + kx*8 + j);
                    a0[4*j+0] = fmaf(v0, w4.x, a0[4*j+0]); a1[4*j+0] = fmaf(v1, w4.x, a1[4*j+0]);
                    a0[4*j+1] = fmaf(v0, w4.y, a0[4*j+1]); a1[4*j+1] = fmaf(v1, w4.y, a1[4*j+1]);
                    a0[4*j+2] = fmaf(v0, w4.z, a0[4*j+2]); a1[4*j+2] = fmaf(v1, w4.z, a1[4*j+2]);
                    a0[4*j+3] = fmaf(v0, w4.w, a0[4*j+3]); a1[4*j+3] = fmaf(v1, w4.w, a1[4*j+3]);
                }
            }
        }
    }
    float* op = g_bufA + (b*32*160 + yo)*160 + xo;
#pragma unroll
    for (int j = 0; j < 32; j++) { op[j*25600] = a0[j]; op[j*25600 + 80] = a1[j]; }
}

// ------------------------- per-(region,channel) stats -> scale/shift -------------------------
__global__ void stats_kernel(const float* __restrict__ gamma, const float* __restrict__ beta) {
    int rc = blockIdx.x;            // 0..511
    int region = rc >> 5;
    int c  = rc & 31;
    int ri = region >> 2;
    int ci = region & 3;
    int tid = threadIdx.x;

    double s = 0.0, ss = 0.0;
    for (int i = tid; i < 64*1600; i += 256) {
        int b = i / 1600;
        int p = i - b*1600;
        int y = ri*40 + p/40;
        int xx = ci*40 + (p % 40);
        float v = g_bufA[((b*32 + c)*160 + y)*160 + xx];
        s  += (double)v;
        ss += (double)v * (double)v;
    }
    __shared__ double sh_s[256], sh_ss[256];
    sh_s[tid] = s; sh_ss[tid] = ss;
    __syncthreads();
    for (int off = 128; off > 0; off >>= 1) {
        if (tid < off) { sh_s[tid] += sh_s[tid+off]; sh_ss[tid] += sh_ss[tid+off]; }
        __syncthreads();
    }
    if (tid == 0) {
        double mean = sh_s[0] / 102400.0;
        double var  = sh_ss[0] / 102400.0 - mean*mean;
        float sc = __ldg(gamma + c) * rsqrtf((float)var + 1e-5f);
        g_scale[rc] = sc;
        g_shift[rc] = __ldg(beta + c) - (float)mean * sc;
    }
}

// ------------------------- normalize + PReLU -------------------------
__global__ void norm_kernel(const float* __restrict__ pa) {
    int t = blockIdx.x * blockDim.x + threadIdx.x;
    if (t >= BATCH*32*160*160) return;
    int xx = t % 160;
    int y  = (t / 160) % 160;
    int c  = (t / 25600) % 32;
    int region = (y / 40) * 4 + (xx / 40);
    float v = g_bufA[t];
    float r = fmaf(v, g_scale[region*32 + c], g_shift[region*32 + c]);
    float a = __ldg(pa);
    g_bufB[t] = (r > 0.0f) ? r : a * r;
}

// ------------------------- region conv: 32->32, 3x3, pad=1 *within region* -------------------------
__global__ void __launch_bounds__(128) rconv_kernel(const float* __restrict__ bias) {
    int t = blockIdx.x * 128 + threadIdx.x;
    if (t >= BATCH * 160 * 80) return;
    int xo = t % 80;
    int yo = (t / 80) % 160;
    int b  = t / (80 * 160);
    int ly = yo % 40;
    int lx = xo % 40;   // same for xo and xo+80 (80 % 40 == 0)

    float a0[32], a1[32];
#pragma unroll
    for (int j = 0; j < 32; j++) { float bv = __ldg(bias + j); a0[j] = bv; a1[j] = bv; }

#pragma unroll
    for (int ty = 0; ty < 3; ty++) {
        int lyy = ly + ty - 1;
        if (lyy < 0 || lyy > 39) continue;
        int iy = yo + ty - 1;
#pragma unroll
        for (int tx = 0; tx < 3; tx++) {
            int lxx = lx + tx - 1;
            if (lxx < 0 || lxx > 39) continue;
            int ixo = xo + tx - 1;
            const float* inp = g_bufB + (b*32*160 + iy)*160 + ixo;
#pragma unroll 4
            for (int ic = 0; ic < 32; ic++) {
                float v0 = __ldg(inp + ic*25600);
                float v1 = __ldg(inp + ic*25600 + 80);
                const float4* w4p = (const float4*)(g_wTr + ((ic*3 + ty)*3 + tx)*32);
#pragma unroll
                for (int j = 0; j < 8; j++) {
                    float4 w4 = __ldg(w4p + j);
                    a0[4*j+0] = fmaf(v0, w4.x, a0[4*j+0]); a1[4*j+0] = fmaf(v1, w4.x, a1[4*j+0]);
                    a0[4*j+1] = fmaf(v0, w4.y, a0[4*j+1]); a1[4*j+1] = fmaf(v1, w4.y, a1[4*j+1]);
                    a0[4*j+2] = fmaf(v0, w4.z, a0[4*j+2]); a1[4*j+2] = fmaf(v1, w4.z, a1[4*j+2]);
                    a0[4*j+3] = fmaf(v0, w4.w, a0[4*j+3]); a1[4*j+3] = fmaf(v1, w4.w, a1[4*j+3]);
                }
            }
        }
    }
    float* op = g_bufA + (b*32*160 + yo)*160 + xo;
#pragma unroll
    for (int j = 0; j < 32; j++) { op[j*25600] = a0[j]; op[j*25600 + 80] = a1[j]; }
}

// ------------------------- 2x2 maxpool, 160->80 -------------------------
__global__ void pool_kernel() {
    int t = blockIdx.x * blockDim.x + threadIdx.x;
    if (t >= BATCH*32*80*80) return;
    int xx = t % 80;
    int y  = (t / 80) % 80;
    int bc = t / 6400;
    const float* p = g_bufA + (bc*160 + 2*y)*160 + 2*xx;
    g_pool[t] = fmaxf(fmaxf(p[0], p[1]), fmaxf(p[160], p[161]));
}

// ------------------------- generic OC=16 direct conv, 2 pixels/thread -------------------------
#define DEFINE_CONV16(NAME, IC, K, S, IH, IW, OH, OW, INBUF, WTBUF, OUTBUF)          \
__global__ void __launch_bounds__(128) NAME(const float* __restrict__ bias) {        \
    const int XP  = ((OW) + 1) / 2;                                                  \
    const int OFF = (OW) - XP;                                                       \
    int t = blockIdx.x * 128 + threadIdx.x;                                          \
    if (t >= BATCH * (OH) * XP) return;                                              \
    int xo = t % XP;                                                                 \
    int yo = (t / XP) % (OH);                                                        \
    int b  = t / (XP * (OH));                                                        \
    float a0[16], a1[16];                                                            \
    _Pragma("unroll")                                                                \
    for (int j = 0; j < 16; j++) { float bv = __ldg(bias + j); a0[j] = bv; a1[j] = bv; } \
    for (int ic = 0; ic < (IC); ic++) {                                              \
        const float* inp = INBUF + ((b*(IC) + ic)*(IH) + yo*(S))*(IW) + xo*(S);      \
        _Pragma("unroll 1")                                                          \
        for (int ky = 0; ky < (K); ky++) {                                           \
            const float* row = inp + ky*(IW);                                        \
            const float4* wrow = (const float4*)(WTBUF + (ic*(K)*(K) + ky*(K))*16);  \
            _Pragma("unroll")                                                        \
            for (int kx = 0; kx < (K); kx++) {                                       \
                float v0 = __ldg(row + kx);                                          \
                float v1 = __ldg(row + OFF*(S) + kx);                                \
                _Pragma("unroll")                                                    \
                for (int j = 0; j < 4; j++) {                                        \
                    float4 w4 = __ldg(wrow + kx*4 + j);                              \
                    a0[4*j+0] = fmaf(v0, w4.x, a0[4*j+0]); a1[4*j+0] = fmaf(v1, w4.x, a1[4*j+0]); \
                    a0[4*j+1] = fmaf(v0, w4.y, a0[4*j+1]); a1[4*j+1] = fmaf(v1, w4.y, a1[4*j+1]); \
                    a0[4*j+2] = fmaf(v0, w4.z, a0[4*j+2]); a1[4*j+2] = fmaf(v1, w4.z, a1[4*j+2]); \
                    a0[4*j+3] = fmaf(v0, w4.w, a0[4*j+3]); a1[4*j+3] = fmaf(v1, w4.w, a1[4*j+3]); \
                }                                                                    \
            }                                                                        \
        }                                                                            \
    }                                                                                \
    float* op = OUTBUF + (b*16*(OH) + yo)*(OW) + xo;                                 \
    _Pragma("unroll")                                                                \
    for (int j = 0; j < 16; j++) {                                                   \
        op[j*(OH)*(OW)]       = a0[j];                                               \
        op[j*(OH)*(OW) + OFF] = a1[j];                                               \
    }                                                                                \
}

DEFINE_CONV16(conv4_kernel, 32, 8, 1, 80, 80, 73, 73, g_pool, g_wT4, g_c4)
DEFINE_CONV16(conv5_kernel, 16, 8, 2, 73, 73, 33, 33, g_c4,   g_wT5, g_c5)
DEFINE_CONV16(conv6_kernel, 16, 6, 1, 33, 33, 28, 28, g_c5,   g_wT6, g_c6)
DEFINE_CONV16(conv7_kernel, 16, 5, 1, 28, 28, 24, 24, g_c6,   g_wT7, g_c7)
DEFINE_CONV16(conv8_kernel, 16, 3, 3, 24, 24,  8,  8, g_c7,   g_wT8, g_c8)

// ------------------------- FC: [64,1024] @ [1024,512]^T + b -------------------------
__global__ void fc_kernel(const float* __restrict__ bias, float* __restrict__ out) {
    __shared__ float sm[1024];
    int b = blockIdx.x;
    int o = threadIdx.x;               // 512 threads
    sm[o]       = g_c8[b*1024 + o];
    sm[o + 512] = g_c8[b*1024 + o + 512];
    __syncthreads();
    float acc = __ldg(bias + o);
#pragma unroll 4
    for (int k = 0; k < 1024; k++)
        acc = fmaf(sm[k], g_wTfc[k*512 + o], acc);
    out[b*512 + o] = acc;
}

// ------------------------- launch -------------------------
static inline int gridFor(long n, int bs) { return (int)((n + bs - 1) / bs); }

extern "C" void kernel_launch(void* const* d_in, const int* in_sizes, int n_in,
                              void* d_out, int out_size) {
    const float* x        = (const float*)d_in[0];
    const float* conv1_w  = (const float*)d_in[1];
    const float* conv1_b  = (const float*)d_in[2];
    const float* bn_gamma = (const float*)d_in[3];
    const float* bn_beta  = (const float*)d_in[4];
    const float* prelu_a  = (const float*)d_in[5];
    const float* rconv_w  = (const float*)d_in[6];
    const float* rconv_b  = (const float*)d_in[7];
    const float* conv4_w  = (const float*)d_in[8];
    const float* conv4_b  = (const float*)d_in[9];
    const float* conv5_w  = (const float*)d_in[10];
    const float* conv5_b  = (const float*)d_in[11];
    const float* conv6_w  = (const float*)d_in[12];
    const float* conv6_b  = (const float*)d_in[13];
    const float* conv7_w  = (const float*)d_in[14];
    const float* conv7_b  = (const float*)d_in[15];
    const float* conv8_w  = (const float*)d_in[16];
    const float* conv8_b  = (const float*)d_in[17];
    const float* fc_w     = (const float*)d_in[18];
    const float* fc_b     = (const float*)d_in[19];
    float* out = (float*)d_out;

    // weight transposes (cheap, every call — deterministic)
    t_w1 <<<gridFor(32*363,  256), 256>>>(conv1_w);
    t_wr <<<gridFor(32*288,  256), 256>>>(rconv_w);
    t_w4 <<<gridFor(16*2048, 256), 256>>>(conv4_w);
    t_w5 <<<gridFor(16*1024, 256), 256>>>(conv5_w);
    t_w6 <<<gridFor(16*576,  256), 256>>>(conv6_w);
    t_w7 <<<gridFor(16*400,  256), 256>>>(conv7_w);
    t_w8 <<<gridFor(16*144,  256), 256>>>(conv8_w);
    t_wfc<<<gridFor(512*1024,256), 256>>>(fc_w);

    conv1_kernel<<<gridFor((long)BATCH*160*80, 128), 128>>>(x, conv1_b);
    stats_kernel<<<512, 256>>>(bn_gamma, bn_beta);
    norm_kernel<<<gridFor((long)BATCH*32*160*160, 256), 256>>>(prelu_a);
    rconv_kernel<<<gridFor((long)BATCH*160*80, 128), 128>>>(rconv_b);
    pool_kernel<<<gridFor((long)BATCH*32*80*80, 256), 256>>>();

    conv4_kernel<<<gridFor((long)BATCH*73*37, 128), 128>>>(conv4_b);
    conv5_kernel<<<gridFor((long)BATCH*33*17, 128), 128>>>(conv5_b);
    conv6_kernel<<<gridFor((long)BATCH*28*14, 128), 128>>>(conv6_b);
    conv7_kernel<<<gridFor((long)BATCH*24*12, 128), 128>>>(conv7_b);
    conv8_kernel<<<gridFor((long)BATCH*8*4,   128), 128>>>(conv8_b);

    fc_kernel<<<BATCH, 512>>>(fc_b, out);
}

// round 3
// speedup vs baseline: 1.3538x; 1.3538x over previous
#include <cuda_runtime.h>
#include <cuda_bf16.h>
#include <cstdint>

#define BATCH 64

// ------------------------- scratch (no allocs allowed) -------------------------
__device__ float g_bufA[BATCH*32*160*160];   // conv1 out
__device__ float g_bufB[BATCH*32*160*160];   // rconv out
__device__ float g_pool[BATCH*32*80*80];
__device__ float g_c4[BATCH*16*73*73];
__device__ float g_c5[BATCH*16*33*33];
__device__ float g_c6[BATCH*16*28*28];
__device__ float g_c7[BATCH*16*24*24];
__device__ float g_c8[BATCH*16*8*8];

__device__ float g_wT5[1024*16];
__device__ float g_wT6[576*16];
__device__ float g_wT7[400*16];
__device__ float g_wT8[144*16];
__device__ float g_wTfc[1024*512];

__device__ float g_scale[512];   // [region(16)][channel(32)]
__device__ float g_shift[512];

// ------------------------- helpers -------------------------
__device__ __forceinline__ uint32_t smem_u32(const void* p) {
    uint32_t a;
    asm("{ .reg .u64 t; cvta.to.shared.u64 t, %1; cvt.u32.u64 %0, t; }" : "=r"(a) : "l"(p));
    return a;
}
__device__ __forceinline__ uint32_t sw128(uint32_t o) { return o ^ ((o >> 3) & 0x70); }

__device__ __forceinline__ void split2(float a, float b, uint32_t& hi, uint32_t& lo) {
    __nv_bfloat162 h = __floats2bfloat162_rn(a, b);
    float ra = a - __bfloat162float(h.x);
    float rb = b - __bfloat162float(h.y);
    __nv_bfloat162 l = __floats2bfloat162_rn(ra, rb);
    hi = *reinterpret_cast<uint32_t*>(&h);
    lo = *reinterpret_cast<uint32_t*>(&l);
}

__device__ __forceinline__ void ldsm4(uint32_t* r, uint32_t addr) {
    asm volatile("ldmatrix.sync.aligned.m8n8.x4.shared.b16 {%0,%1,%2,%3}, [%4];"
                 : "=r"(r[0]), "=r"(r[1]), "=r"(r[2]), "=r"(r[3]) : "r"(addr));
}

__device__ __forceinline__ void mma_bf16(float* c,
        uint32_t a0, uint32_t a1, uint32_t a2, uint32_t a3,
        uint32_t b0, uint32_t b1) {
    asm volatile(
        "mma.sync.aligned.m16n8k16.row.col.f32.bf16.bf16.f32 "
        "{%0,%1,%2,%3}, {%4,%5,%6,%7}, {%8,%9}, {%0,%1,%2,%3};"
        : "+f"(c[0]), "+f"(c[1]), "+f"(c[2]), "+f"(c[3])
        : "r"(a0), "r"(a1), "r"(a2), "r"(a3), "r"(b0), "r"(b1));
}

// tile byte offsets inside static smem
#define OFF_AHI 0
#define OFF_ALO 16384
#define OFF_BHI 32768
#define OFF_BLO 36864
#define OFF_SC  40960
#define OFF_SH  43008

// issue the 4 k-steps of one 64-wide K chunk for N=32 tiles
__device__ __forceinline__ void mma_chunk_n32(uint32_t sb, int wid, int lane, float* acc) {
#pragma unroll
    for (int ks = 0; ks < 4; ks++) {
        uint32_t a_hi[8], a_lo[8], b_hi[8], b_lo[8];
        uint32_t abyte = (uint32_t)((wid*32 + (lane & 15))*128 + (ks*16 + ((lane >> 4) << 3))*2);
        ldsm4(&a_hi[0], sb + OFF_AHI + sw128(abyte));
        ldsm4(&a_hi[4], sb + OFF_AHI + sw128(abyte) + 2048);
        ldsm4(&a_lo[0], sb + OFF_ALO + sw128(abyte));
        ldsm4(&a_lo[4], sb + OFF_ALO + sw128(abyte) + 2048);
        uint32_t bbyte = (uint32_t)(((((lane >> 4) << 3) + (lane & 7))*128) + (ks*16 + (lane & 8))*2);
        ldsm4(&b_hi[0], sb + OFF_BHI + sw128(bbyte));
        ldsm4(&b_hi[4], sb + OFF_BHI + sw128(bbyte) + 2048);
        ldsm4(&b_lo[0], sb + OFF_BLO + sw128(bbyte));
        ldsm4(&b_lo[4], sb + OFF_BLO + sw128(bbyte) + 2048);
#pragma unroll
        for (int mt = 0; mt < 2; mt++) {
#pragma unroll
            for (int nt = 0; nt < 4; nt++) {
                float* cc = acc + (mt*4 + nt)*4;
                const uint32_t* A  = a_hi + mt*4;
                const uint32_t* Al = a_lo + mt*4;
                uint32_t bh0 = b_hi[nt*2], bh1 = b_hi[nt*2+1];
                uint32_t bl0 = b_lo[nt*2], bl1 = b_lo[nt*2+1];
                mma_bf16(cc, A[0],A[1],A[2],A[3],   bh0, bh1);
                mma_bf16(cc, Al[0],Al[1],Al[2],Al[3], bh0, bh1);
                mma_bf16(cc, A[0],A[1],A[2],A[3],   bl0, bl1);
            }
        }
    }
}

// epilogue: stage acc (N=32) into smem (stride 33) then coalesced gmem store
__device__ __forceinline__ void epilogue_n32(char* smem, int wid, int lane, int tid,
                                             const float* acc, float* op,
                                             const float* __restrict__ bias) {
    float* stg = (float*)smem;
#pragma unroll
    for (int mt = 0; mt < 2; mt++)
#pragma unroll
        for (int nt = 0; nt < 4; nt++)
#pragma unroll
            for (int r = 0; r < 4; r++) {
                int row = wid*32 + mt*16 + (lane >> 2) + ((r >> 1) << 3);
                int col = nt*8 + ((lane & 3) << 1) + (r & 1);
                stg[row*33 + col] = acc[(mt*4 + nt)*4 + r];
            }
    __syncthreads();
#pragma unroll
    for (int j = 0; j < 32; j++)
        op[j*25600] = stg[tid*33 + j] + __ldg(bias + j);
}

// ------------------------- conv1: implicit GEMM, M=128 pix, N=32, K=363 -------------------------
__global__ void __launch_bounds__(128) conv1_mma(const float* __restrict__ x,
                                                 const float* __restrict__ w,
                                                 const float* __restrict__ bias) {
    __shared__ uint32_t smem_u[10240];           // 40960 B
    char* smem = (char*)smem_u;
    uint32_t sb = smem_u32(smem);
    int tid = threadIdx.x, wid = tid >> 5, lane = tid & 31;

    int p  = blockIdx.x * 128 + tid;
    int xo = p % 160, yo = (p / 160) % 160, b = p / 25600;
    const float* xin = x + (b * 3 * 170 + yo) * 170 + xo;

    float acc[32];
#pragma unroll
    for (int i = 0; i < 32; i++) acc[i] = 0.f;

    for (int c = 0; c < 6; c++) {
        int k0 = c * 64;
#pragma unroll 8
        for (int i = 0; i < 32; i++) {
            int k = k0 + 2 * i;
            float v0 = 0.f, v1 = 0.f;
            if (k < 363) {
                int ic = (k >= 242) ? 2 : ((k >= 121) ? 1 : 0);
                int r  = k - ic * 121;
                int ky = r / 11, kx = r - ky * 11;
                v0 = __ldg(xin + ic * 28900 + ky * 170 + kx);
                int k1 = k + 1;
                if (k1 < 363) {
                    int ic1 = (k1 >= 242) ? 2 : ((k1 >= 121) ? 1 : 0);
                    int r1  = k1 - ic1 * 121;
                    int ky1 = r1 / 11, kx1 = r1 - ky1 * 11;
                    v1 = __ldg(xin + ic1 * 28900 + ky1 * 170 + kx1);
                }
            }
            uint32_t hi, lo; split2(v0, v1, hi, lo);
            uint32_t off = sw128((uint32_t)(tid * 128 + i * 4));
            *(uint32_t*)(smem + OFF_AHI + off) = hi;
            *(uint32_t*)(smem + OFF_ALO + off) = lo;
        }
#pragma unroll
        for (int e = tid; e < 1024; e += 128) {
            int oc = e >> 5, i = e & 31;
            int k = k0 + 2 * i;
            float v0 = (k < 363) ? __ldg(w + oc * 363 + k) : 0.f;
            float v1 = (k + 1 < 363) ? __ldg(w + oc * 363 + k + 1) : 0.f;
            uint32_t hi, lo; split2(v0, v1, hi, lo);
            uint32_t off = sw128((uint32_t)(oc * 128 + i * 4));
            *(uint32_t*)(smem + OFF_BHI + off) = hi;
            *(uint32_t*)(smem + OFF_BLO + off) = lo;
        }
        __syncthreads();
        mma_chunk_n32(sb, wid, lane, acc);
        __syncthreads();
    }
    float* op = g_bufA + (b * 32 * 160 + yo) * 160 + xo;
    epilogue_n32(smem, wid, lane, tid, acc, op, bias);
}

// ------------------------- per-(region,channel) stats -> scale/shift -------------------------
__global__ void stats_kernel(const float* __restrict__ gamma, const float* __restrict__ beta) {
    int rc = blockIdx.x;
    int region = rc >> 5;
    int c  = rc & 31;
    int ri = region >> 2, ci = region & 3;
    int tid = threadIdx.x;

    double s = 0.0, ss = 0.0;
    for (int i = tid; i < 64 * 1600; i += 256) {
        int b = i / 1600;
        int p = i - b * 1600;
        int y = ri * 40 + p / 40;
        int xx = ci * 40 + (p % 40);
        float v = g_bufA[((b * 32 + c) * 160 + y) * 160 + xx];
        s += (double)v; ss += (double)v * (double)v;
    }
    __shared__ double sh_s[256], sh_ss[256];
    sh_s[tid] = s; sh_ss[tid] = ss;
    __syncthreads();
    for (int off = 128; off > 0; off >>= 1) {
        if (tid < off) { sh_s[tid] += sh_s[tid + off]; sh_ss[tid] += sh_ss[tid + off]; }
        __syncthreads();
    }
    if (tid == 0) {
        double mean = sh_s[0] / 102400.0;
        double var  = sh_ss[0] / 102400.0 - mean * mean;
        float sc = __ldg(gamma + c) * rsqrtf((float)var + 1e-5f);
        g_scale[rc] = sc;
        g_shift[rc] = __ldg(beta + c) - (float)mean * sc;
    }
}

// ------------------------- rconv: implicit GEMM + fused norm/PReLU, N=32, K=288 -------------------------
__global__ void __launch_bounds__(128) rconv_mma(const float* __restrict__ w,
                                                 const float* __restrict__ bias,
                                                 const float* __restrict__ pa) {
    __shared__ uint32_t smem_u[11264];           // 45056 B
    char* smem = (char*)smem_u;
    uint32_t sb = smem_u32(smem);
    int tid = threadIdx.x, wid = tid >> 5, lane = tid & 31;

    float* ssc = (float*)(smem + OFF_SC);
    float* ssh = (float*)(smem + OFF_SH);
    for (int i = tid; i < 512; i += 128) { ssc[i] = g_scale[i]; ssh[i] = g_shift[i]; }

    int p  = blockIdx.x * 128 + tid;
    int xo = p % 160, yo = (p / 160) % 160, b = p / 25600;
    int lx = xo % 40, ly = yo % 40;
    int rcb = ((yo / 40) * 4 + (xo / 40)) * 32;
    float alpha = __ldg(pa);

    float acc[32];
#pragma unroll
    for (int i = 0; i < 32; i++) acc[i] = 0.f;
    __syncthreads();

    for (int c = 0; c < 5; c++) {
        int k0 = c * 64;
#pragma unroll 8
        for (int i = 0; i < 32; i++) {
            int k  = k0 + 2 * i;
            int t  = k >> 5;
            int ic = k & 31;          // even
            float v0 = 0.f, v1 = 0.f;
            if (t < 9) {
                int ty = t / 3, tx = t - ty * 3;
                if ((unsigned)(ly + ty - 1) < 40u && (unsigned)(lx + tx - 1) < 40u) {
                    const float* q = g_bufA + ((b * 32 + ic) * 160 + yo + ty - 1) * 160 + xo + tx - 1;
                    float u0 = __ldg(q);
                    float u1 = __ldg(q + 25600);
                    float r0 = fmaf(u0, ssc[rcb + ic],     ssh[rcb + ic]);
                    float r1 = fmaf(u1, ssc[rcb + ic + 1], ssh[rcb + ic + 1]);
                    v0 = (r0 > 0.f) ? r0 : alpha * r0;
                    v1 = (r1 > 0.f) ? r1 : alpha * r1;
                }
            }
            uint32_t hi, lo; split2(v0, v1, hi, lo);
            uint32_t off = sw128((uint32_t)(tid * 128 + i * 4));
            *(uint32_t*)(smem + OFF_AHI + off) = hi;
            *(uint32_t*)(smem + OFF_ALO + off) = lo;
        }
#pragma unroll
        for (int e = tid; e < 1024; e += 128) {
            int oc = e >> 5, i = e & 31;
            int k  = k0 + 2 * i;
            int t  = k >> 5, ic = k & 31;
            float v0 = 0.f, v1 = 0.f;
            if (t < 9) {
                v0 = __ldg(w + oc * 288 + ic * 9 + t);
                v1 = __ldg(w + oc * 288 + (ic + 1) * 9 + t);
            }
            uint32_t hi, lo; split2(v0, v1, hi, lo);
            uint32_t off = sw128((uint32_t)(oc * 128 + i * 4));
            *(uint32_t*)(smem + OFF_BHI + off) = hi;
            *(uint32_t*)(smem + OFF_BLO + off) = lo;
        }
        __syncthreads();
        mma_chunk_n32(sb, wid, lane, acc);
        __syncthreads();
    }
    float* op = g_bufB + (b * 32 * 160 + yo) * 160 + xo;
    epilogue_n32(smem, wid, lane, tid, acc, op, bias);
}

// ------------------------- 2x2 maxpool, 160->80 -------------------------
__global__ void pool_kernel() {
    int t = blockIdx.x * blockDim.x + threadIdx.x;
    if (t >= BATCH * 32 * 80 * 80) return;
    int xx = t % 80;
    int y  = (t / 80) % 80;
    int bc = t / 6400;
    const float* p = g_bufB + (bc * 160 + 2 * y) * 160 + 2 * xx;
    g_pool[t] = fmaxf(fmaxf(p[0], p[1]), fmaxf(p[160], p[161]));
}

// ------------------------- conv4: implicit GEMM, N=16, K=2048 -------------------------
#define CONV4_M (BATCH * 73 * 73)
#define C4_BHI 32768
#define C4_BLO 34816
__global__ void __launch_bounds__(128) conv4_mma(const float* __restrict__ w,
                                                 const float* __restrict__ bias) {
    __shared__ uint32_t smem_u[9216];            // 36864 B
    char* smem = (char*)smem_u;
    uint32_t sb = smem_u32(smem);
    int tid = threadIdx.x, wid = tid >> 5, lane = tid & 31;

    int p  = blockIdx.x * 128 + tid;
    bool pv = p < CONV4_M;
    int pp = pv ? p : 0;
    int xo = pp % 73, yo = (pp / 73) % 73, b = pp / 5329;
    const float* pin = g_pool + (b * 32 * 80 + yo) * 80 + xo;

    float acc[16];
#pragma unroll
    for (int i = 0; i < 16; i++) acc[i] = 0.f;

    for (int c = 0; c < 32; c++) {
        int k0 = c * 64;
#pragma unroll 8
        for (int i = 0; i < 32; i++) {
            int k  = k0 + 2 * i;
            int ic = k >> 6;
            int r  = k & 63;
            int ky = r >> 3, kx = r & 7;   // kx even
            float v0 = 0.f, v1 = 0.f;
            if (pv) {
                const float* q = pin + ic * 6400 + ky * 80 + kx;
                v0 = __ldg(q);
                v1 = __ldg(q + 1);
            }
            uint32_t hi, lo; split2(v0, v1, hi, lo);
            uint32_t off = sw128((uint32_t)(tid * 128 + i * 4));
            *(uint32_t*)(smem + OFF_AHI + off) = hi;
            *(uint32_t*)(smem + OFF_ALO + off) = lo;
        }
#pragma unroll
        for (int e = tid; e < 512; e += 128) {
            int oc = e >> 5, i = e & 31;
            int k  = k0 + 2 * i;
            float v0 = __ldg(w + oc * 2048 + k);
            float v1 = __ldg(w + oc * 2048 + k + 1);
            uint32_t hi, lo; split2(v0, v1, hi, lo);
            uint32_t off = sw128((uint32_t)(oc * 128 + i * 4));
            *(uint32_t*)(smem + C4_BHI + off) = hi;
            *(uint32_t*)(smem + C4_BLO + off) = lo;
        }
        __syncthreads();
#pragma unroll
        for (int ks = 0; ks < 4; ks++) {
            uint32_t a_hi[8], a_lo[8], b_hi[4], b_lo[4];
            uint32_t abyte = (uint32_t)((wid*32 + (lane & 15))*128 + (ks*16 + ((lane >> 4) << 3))*2);
            ldsm4(&a_hi[0], sb + OFF_AHI + sw128(abyte));
            ldsm4(&a_hi[4], sb + OFF_AHI + sw128(abyte) + 2048);
            ldsm4(&a_lo[0], sb + OFF_ALO + sw128(abyte));
            ldsm4(&a_lo[4], sb + OFF_ALO + sw128(abyte) + 2048);
            uint32_t bbyte = (uint32_t)(((((lane >> 4) << 3) + (lane & 7))*128) + (ks*16 + (lane & 8))*2);
            ldsm4(b_hi, sb + C4_BHI + sw128(bbyte));
            ldsm4(b_lo, sb + C4_BLO + sw128(bbyte));
#pragma unroll
            for (int mt = 0; mt < 2; mt++) {
#pragma unroll
                for (int nt = 0; nt < 2; nt++) {
                    float* cc = acc + (mt*2 + nt)*4;
                    const uint32_t* A  = a_hi + mt*4;
                    const uint32_t* Al = a_lo + mt*4;
                    uint32_t bh0 = b_hi[nt*2], bh1 = b_hi[nt*2+1];
                    uint32_t bl0 = b_lo[nt*2], bl1 = b_lo[nt*2+1];
                    mma_bf16(cc, A[0],A[1],A[2],A[3],   bh0, bh1);
                    mma_bf16(cc, Al[0],Al[1],Al[2],Al[3], bh0, bh1);
                    mma_bf16(cc, A[0],A[1],A[2],A[3],   bl0, bl1);
                }
            }
        }
        __syncthreads();
    }
    // stage + store
    float* stg = (float*)smem;
#pragma unroll
    for (int mt = 0; mt < 2; mt++)
#pragma unroll
        for (int nt = 0; nt < 2; nt++)
#pragma unroll
            for (int r = 0; r < 4; r++) {
                int row = wid*32 + mt*16 + (lane >> 2) + ((r >> 1) << 3);
                int col = nt*8 + ((lane & 3) << 1) + (r & 1);
                stg[row*17 + col] = acc[(mt*2 + nt)*4 + r];
            }
    __syncthreads();
    if (pv) {
        float* op = g_c4 + (b * 16 * 73 + yo) * 73 + xo;
#pragma unroll
        for (int j = 0; j < 16; j++)
            op[j * 5329] = stg[tid*17 + j] + __ldg(bias + j);
    }
}

// ------------------------- weight transpose for remaining direct convs -------------------------
#define DEFINE_TRANS(NAME, OC, R, DST)                                        \
__global__ void NAME(const float* __restrict__ w) {                           \
    int e = blockIdx.x * blockDim.x + threadIdx.x;                            \
    if (e < (OC)*(R)) {                                                       \
        int oc = e / (R);                                                     \
        int r  = e - oc * (R);                                                \
        DST[r*(OC) + oc] = w[e];                                              \
    }                                                                         \
}
DEFINE_TRANS(t_w5,  16, 1024, g_wT5)
DEFINE_TRANS(t_w6,  16,  576, g_wT6)
DEFINE_TRANS(t_w7,  16,  400, g_wT7)
DEFINE_TRANS(t_w8,  16,  144, g_wT8)
DEFINE_TRANS(t_wfc, 512, 1024, g_wTfc)

// ------------------------- generic OC=16 direct conv, 2 pixels/thread -------------------------
#define DEFINE_CONV16(NAME, IC, K, S, IH, IW, OH, OW, INBUF, WTBUF, OUTBUF)          \
__global__ void __launch_bounds__(128) NAME(const float* __restrict__ bias) {        \
    const int XP  = ((OW) + 1) / 2;                                                  \
    const int OFF = (OW) - XP;                                                       \
    int t = blockIdx.x * 128 + threadIdx.x;                                          \
    if (t >= BATCH * (OH) * XP) return;                                              \
    int xo = t % XP;                                                                 \
    int yo = (t / XP) % (OH);                                                        \
    int b  = t / (XP * (OH));                                                        \
    float a0[16], a1[16];                                                            \
    _Pragma("unroll")                                                                \
    for (int j = 0; j < 16; j++) { float bv = __ldg(bias + j); a0[j] = bv; a1[j] = bv; } \
    for (int ic = 0; ic < (IC); ic++) {                                              \
        const float* inp = INBUF + ((b*(IC) + ic)*(IH) + yo*(S))*(IW) + xo*(S);      \
        _Pragma("unroll 1")                                                          \
        for (int ky = 0; ky < (K); ky++) {                                           \
            const float* row = inp + ky*(IW);                                        \
            const float4* wrow = (const float4*)(WTBUF + (ic*(K)*(K) + ky*(K))*16);  \
            _Pragma("unroll")                                                        \
            for (int kx = 0; kx < (K); kx++) {                                       \
                float v0 = __ldg(row + kx);                                          \
                float v1 = __ldg(row + OFF*(S) + kx);                                \
                _Pragma("unroll")                                                    \
                for (int j = 0; j < 4; j++) {                                        \
                    float4 w4 = __ldg(wrow + kx*4 + j);                              \
                    a0[4*j+0] = fmaf(v0, w4.x, a0[4*j+0]); a1[4*j+0] = fmaf(v1, w4.x, a1[4*j+0]); \
                    a0[4*j+1] = fmaf(v0, w4.y, a0[4*j+1]); a1[4*j+1] = fmaf(v1, w4.y, a1[4*j+1]); \
                    a0[4*j+2] = fmaf(v0, w4.z, a0[4*j+2]); a1[4*j+2] = fmaf(v1, w4.z, a1[4*j+2]); \
                    a0[4*j+3] = fmaf(v0, w4.w, a0[4*j+3]); a1[4*j+3] = fmaf(v1, w4.w, a1[4*j+3]); \
                }                                                                    \
            }                                                                        \
        }                                                                            \
    }                                                                                \
    float* op = OUTBUF + (b*16*(OH) + yo)*(OW) + xo;                                 \
    _Pragma("unroll")                                                                \
    for (int j = 0; j < 16; j++) {                                                   \
        op[j*(OH)*(OW)]       = a0[j];                                               \
        op[j*(OH)*(OW) + OFF] = a1[j];                                               \
    }                                                                                \
}

DEFINE_CONV16(conv5_kernel, 16, 8, 2, 73, 73, 33, 33, g_c4, g_wT5, g_c5)
DEFINE_CONV16(conv6_kernel, 16, 6, 1, 33, 33, 28, 28, g_c5, g_wT6, g_c6)
DEFINE_CONV16(conv7_kernel, 16, 5, 1, 28, 28, 24, 24, g_c6, g_wT7, g_c7)
DEFINE_CONV16(conv8_kernel, 16, 3, 3, 24, 24,  8,  8, g_c7, g_wT8, g_c8)

// ------------------------- FC -------------------------
__global__ void fc_kernel(const float* __restrict__ bias, float* __restrict__ out) {
    __shared__ float sm[1024];
    int b = blockIdx.x;
    int o = threadIdx.x;
    sm[o]       = g_c8[b * 1024 + o];
    sm[o + 512] = g_c8[b * 1024 + o + 512];
    __syncthreads();
    float acc = __ldg(bias + o);
#pragma unroll 4
    for (int k = 0; k < 1024; k++)
        acc = fmaf(sm[k], g_wTfc[k * 512 + o], acc);
    out[b * 512 + o] = acc;
}

// ------------------------- launch -------------------------
static inline int gridFor(long n, int bs) { return (int)((n + bs - 1) / bs); }

extern "C" void kernel_launch(void* const* d_in, const int* in_sizes, int n_in,
                              void* d_out, int out_size) {
    const float* x        = (const float*)d_in[0];
    const float* conv1_w  = (const float*)d_in[1];
    const float* conv1_b  = (const float*)d_in[2];
    const float* bn_gamma = (const float*)d_in[3];
    const float* bn_beta  = (const float*)d_in[4];
    const float* prelu_a  = (const float*)d_in[5];
    const float* rconv_w  = (const float*)d_in[6];
    const float* rconv_b  = (const float*)d_in[7];
    const float* conv4_w  = (const float*)d_in[8];
    const float* conv4_b  = (const float*)d_in[9];
    const float* conv5_b  = (const float*)d_in[11];
    const float* conv6_b  = (const float*)d_in[13];
    const float* conv7_b  = (const float*)d_in[15];
    const float* conv8_b  = (const float*)d_in[17];
    const float* fc_b     = (const float*)d_in[19];
    float* out = (float*)d_out;

    t_w5 <<<gridFor(16*1024, 256), 256>>>((const float*)d_in[10]);
    t_w6 <<<gridFor(16*576,  256), 256>>>((const float*)d_in[12]);
    t_w7 <<<gridFor(16*400,  256), 256>>>((const float*)d_in[14]);
    t_w8 <<<gridFor(16*144,  256), 256>>>((const float*)d_in[16]);
    t_wfc<<<gridFor(512*1024,256), 256>>>((const float*)d_in[18]);

    conv1_mma<<<12800, 128>>>(x, conv1_w, conv1_b);
    stats_kernel<<<512, 256>>>(bn_gamma, bn_beta);
    rconv_mma<<<12800, 128>>>(rconv_w, rconv_b, prelu_a);
    pool_kernel<<<gridFor((long)BATCH*32*80*80, 256), 256>>>();

    conv4_mma<<<gridFor(CONV4_M, 128), 128>>>(conv4_w, conv4_b);
    conv5_kernel<<<gridFor((long)BATCH*33*17, 128), 128>>>(conv5_b);
    conv6_kernel<<<gridFor((long)BATCH*28*14, 128), 128>>>(conv6_b);
    conv7_kernel<<<gridFor((long)BATCH*24*12, 128), 128>>>(conv7_b);
    conv8_kernel<<<gridFor((long)BATCH*8*4,   128), 128>>>(conv8_b);

    fc_kernel<<<BATCH, 512>>>(fc_b, out);
}

// round 4
// speedup vs baseline: 1.6812x; 1.2419x over previous
#include <cuda_runtime.h>
#include <cuda_bf16.h>
#include <cstdint>

#define BATCH 64

// ------------------------- scratch (no allocs allowed) -------------------------
__device__ float    g_bufA[BATCH*32*160*160];   // conv1 out (fp32, for stats)
__device__ float    g_bufB[BATCH*32*160*160];   // rconv out (fp32, for pool)
__device__ uint32_t g_xHL[BATCH*3*170*170];     // input, packed hi/lo bf16
__device__ uint32_t g_actHL[BATCH*32*160*160];  // norm+PReLU(conv1 out), packed
__device__ uint32_t g_poolHL[BATCH*32*80*80];   // pooled, packed
__device__ float g_c4[BATCH*16*73*73];
__device__ float g_c5[BATCH*16*33*33];
__device__ float g_c6[BATCH*16*28*28];
__device__ float g_c7[BATCH*16*24*24];
__device__ float g_c8[BATCH*16*8*8];

__device__ uint32_t g_w1HL[32*384];    // conv1 w, K padded 363->384
__device__ uint32_t g_wrHL[32*320];    // rconv w, reordered k=t*32+ic, padded 288->320
__device__ uint32_t g_w4HL[16*2048];   // conv4 w

__device__ float g_wT5[1024*16];
__device__ float g_wT6[576*16];
__device__ float g_wT7[400*16];
__device__ float g_wT8[144*16];
__device__ float g_wTfc[1024*512];

__device__ float g_scale[512];   // [region(16)][channel(32)]
__device__ float g_shift[512];

// ------------------------- helpers -------------------------
__device__ __forceinline__ uint32_t smem_u32(const void* p) {
    uint32_t a;
    asm("{ .reg .u64 t; cvta.to.shared.u64 t, %1; cvt.u32.u64 %0, t; }" : "=r"(a) : "l"(p));
    return a;
}
__device__ __forceinline__ uint32_t sw128(uint32_t o) { return o ^ ((o >> 3) & 0x70); }

__device__ __forceinline__ uint32_t packHL(float v) {
    __nv_bfloat16 h = __float2bfloat16(v);
    float r = v - __bfloat162float(h);
    __nv_bfloat16 l = __float2bfloat16(r);
    uint16_t hb = *reinterpret_cast<uint16_t*>(&h);
    uint16_t lb = *reinterpret_cast<uint16_t*>(&l);
    return (uint32_t)hb | ((uint32_t)lb << 16);
}

__device__ __forceinline__ void ldsm4(uint32_t* r, uint32_t addr) {
    asm volatile("ldmatrix.sync.aligned.m8n8.x4.shared.b16 {%0,%1,%2,%3}, [%4];"
                 : "=r"(r[0]), "=r"(r[1]), "=r"(r[2]), "=r"(r[3]) : "r"(addr));
}

__device__ __forceinline__ void mma_bf16(float* c,
        uint32_t a0, uint32_t a1, uint32_t a2, uint32_t a3,
        uint32_t b0, uint32_t b1) {
    asm volatile(
        "mma.sync.aligned.m16n8k16.row.col.f32.bf16.bf16.f32 "
        "{%0,%1,%2,%3}, {%4,%5,%6,%7}, {%8,%9}, {%0,%1,%2,%3};"
        : "+f"(c[0]), "+f"(c[1]), "+f"(c[2]), "+f"(c[3])
        : "r"(a0), "r"(a1), "r"(a2), "r"(a3), "r"(b0), "r"(b1));
}

// tile byte offsets inside static smem
#define OFF_AHI 0
#define OFF_ALO 16384
#define OFF_BHI 32768
#define OFF_BLO 36864

// issue the 4 k-steps of one 64-wide K chunk for N=32 tiles
__device__ __forceinline__ void mma_chunk_n32(uint32_t sb, int wid, int lane, float* acc) {
#pragma unroll
    for (int ks = 0; ks < 4; ks++) {
        uint32_t a_hi[8], a_lo[8], b_hi[8], b_lo[8];
        uint32_t abyte = (uint32_t)((wid*32 + (lane & 15))*128 + (ks*16 + ((lane >> 4) << 3))*2);
        ldsm4(&a_hi[0], sb + OFF_AHI + sw128(abyte));
        ldsm4(&a_hi[4], sb + OFF_AHI + sw128(abyte) + 2048);
        ldsm4(&a_lo[0], sb + OFF_ALO + sw128(abyte));
        ldsm4(&a_lo[4], sb + OFF_ALO + sw128(abyte) + 2048);
        uint32_t bbyte = (uint32_t)(((((lane >> 4) << 3) + (lane & 7))*128) + (ks*16 + (lane & 8))*2);
        ldsm4(&b_hi[0], sb + OFF_BHI + sw128(bbyte));
        ldsm4(&b_hi[4], sb + OFF_BHI + sw128(bbyte) + 2048);
        ldsm4(&b_lo[0], sb + OFF_BLO + sw128(bbyte));
        ldsm4(&b_lo[4], sb + OFF_BLO + sw128(bbyte) + 2048);
#pragma unroll
        for (int mt = 0; mt < 2; mt++) {
#pragma unroll
            for (int nt = 0; nt < 4; nt++) {
                float* cc = acc + (mt*4 + nt)*4;
                const uint32_t* A  = a_hi + mt*4;
                const uint32_t* Al = a_lo + mt*4;
                uint32_t bh0 = b_hi[nt*2], bh1 = b_hi[nt*2+1];
                uint32_t bl0 = b_lo[nt*2], bl1 = b_lo[nt*2+1];
                mma_bf16(cc, A[0],A[1],A[2],A[3],   bh0, bh1);
                mma_bf16(cc, Al[0],Al[1],Al[2],Al[3], bh0, bh1);
                mma_bf16(cc, A[0],A[1],A[2],A[3],   bl0, bl1);
            }
        }
    }
}

// epilogue: stage acc (N=32) into smem (stride 33) then coalesced gmem store
__device__ __forceinline__ void epilogue_n32(char* smem, int wid, int lane, int tid,
                                             const float* acc, float* op,
                                             const float* __restrict__ bias) {
    float* stg = (float*)smem;
#pragma unroll
    for (int mt = 0; mt < 2; mt++)
#pragma unroll
        for (int nt = 0; nt < 4; nt++)
#pragma unroll
            for (int r = 0; r < 4; r++) {
                int row = wid*32 + mt*16 + (lane >> 2) + ((r >> 1) << 3);
                int col = nt*8 + ((lane & 3) << 1) + (r & 1);
                stg[row*33 + col] = acc[(mt*4 + nt)*4 + r];
            }
    __syncthreads();
#pragma unroll
    for (int j = 0; j < 32; j++)
        op[j*25600] = stg[tid*33 + j] + __ldg(bias + j);
}

// ------------------------- pre-pass kernels -------------------------
__global__ void split_x(const float* __restrict__ x) {
    int t = blockIdx.x * blockDim.x + threadIdx.x;
    if (t < BATCH*3*170*170) g_xHL[t] = packHL(x[t]);
}

__global__ void t_w1hl(const float* __restrict__ w) {
    int e = blockIdx.x * blockDim.x + threadIdx.x;   // 32*384
    if (e < 32*384) {
        int oc = e / 384, k = e - oc*384;
        g_w1HL[e] = (k < 363) ? packHL(w[oc*363 + k]) : 0u;
    }
}
__global__ void t_wrhl(const float* __restrict__ w) {
    int e = blockIdx.x * blockDim.x + threadIdx.x;   // 32*320
    if (e < 32*320) {
        int oc = e / 320, k = e - oc*320;
        int t9 = k >> 5, ic = k & 31;
        g_wrHL[e] = (t9 < 9) ? packHL(w[oc*288 + ic*9 + t9]) : 0u;
    }
}
__global__ void t_w4hl(const float* __restrict__ w) {
    int e = blockIdx.x * blockDim.x + threadIdx.x;   // 16*2048
    if (e < 16*2048) g_w4HL[e] = packHL(w[e]);
}

// norm + PReLU + split, one pass (rconv reads each element 9x)
__global__ void act_kernel(const float* __restrict__ pa) {
    int t = blockIdx.x * blockDim.x + threadIdx.x;
    if (t >= BATCH*32*160*160) return;
    int xx = t % 160;
    int y  = (t / 160) % 160;
    int c  = (t / 25600) % 32;
    int region = (y / 40) * 4 + (xx / 40);
    float v = g_bufA[t];
    float r = fmaf(v, g_scale[region*32 + c], g_shift[region*32 + c]);
    float a = __ldg(pa);
    g_actHL[t] = packHL((r > 0.0f) ? r : a * r);
}

// ------------------------- conv1: implicit GEMM, M=128 pix, N=32, K=384(363) -------------------------
__global__ void __launch_bounds__(128) conv1_mma(const float* __restrict__ bias) {
    __shared__ uint32_t smem_u[10240];           // 40960 B tiles
    __shared__ int soffs[384];
    char* smem = (char*)smem_u;
    uint32_t sb = smem_u32(smem);
    int tid = threadIdx.x, wid = tid >> 5, lane = tid & 31;

    for (int k = tid; k < 384; k += 128) {
        if (k < 363) {
            int ic = k / 121;
            int r  = k - ic * 121;
            int ky = r / 11, kx = r - ky * 11;
            soffs[k] = ic * 28900 + ky * 170 + kx;
        } else soffs[k] = -1;
    }
    __syncthreads();

    int p  = blockIdx.x * 128 + tid;
    int xo = p % 160, yo = (p / 160) % 160, b = p / 25600;
    const uint32_t* xin = g_xHL + b * 86700 + yo * 170 + xo;

    float acc[32];
#pragma unroll
    for (int i = 0; i < 32; i++) acc[i] = 0.f;

    for (int c = 0; c < 6; c++) {
        int k0 = c * 64;
#pragma unroll 8
        for (int i = 0; i < 32; i++) {
            int2 o2 = *(const int2*)(soffs + k0 + 2*i);
            uint32_t v0 = (o2.x >= 0) ? __ldg(xin + o2.x) : 0u;
            uint32_t v1 = (o2.y >= 0) ? __ldg(xin + o2.y) : 0u;
            uint32_t off = sw128((uint32_t)(tid * 128 + i * 4));
            *(uint32_t*)(smem + OFF_AHI + off) = __byte_perm(v0, v1, 0x5410);
            *(uint32_t*)(smem + OFF_ALO + off) = __byte_perm(v0, v1, 0x7632);
        }
#pragma unroll
        for (int e = tid; e < 1024; e += 128) {
            int oc = e >> 5, i = e & 31;
            uint2 w2 = __ldg((const uint2*)(g_w1HL + oc*384 + k0 + 2*i));
            uint32_t off = sw128((uint32_t)(oc * 128 + i * 4));
            *(uint32_t*)(smem + OFF_BHI + off) = __byte_perm(w2.x, w2.y, 0x5410);
            *(uint32_t*)(smem + OFF_BLO + off) = __byte_perm(w2.x, w2.y, 0x7632);
        }
        __syncthreads();
        mma_chunk_n32(sb, wid, lane, acc);
        __syncthreads();
    }
    float* op = g_bufA + (b * 32 * 160 + yo) * 160 + xo;
    epilogue_n32(smem, wid, lane, tid, acc, op, bias);
}

// ------------------------- per-(region,channel) stats -> scale/shift -------------------------
__global__ void stats_kernel(const float* __restrict__ gamma, const float* __restrict__ beta) {
    int rc = blockIdx.x;
    int region = rc >> 5;
    int c  = rc & 31;
    int ri = region >> 2, ci = region & 3;
    int tid = threadIdx.x;

    double s = 0.0, ss = 0.0;
    for (int i = tid; i < 64 * 1600; i += 256) {
        int b = i / 1600;
        int p = i - b * 1600;
        int y = ri * 40 + p / 40;
        int xx = ci * 40 + (p % 40);
        float v = g_bufA[((b * 32 + c) * 160 + y) * 160 + xx];
        s += (double)v; ss += (double)v * (double)v;
    }
    __shared__ double sh_s[256], sh_ss[256];
    sh_s[tid] = s; sh_ss[tid] = ss;
    __syncthreads();
    for (int off = 128; off > 0; off >>= 1) {
        if (tid < off) { sh_s[tid] += sh_s[tid + off]; sh_ss[tid] += sh_ss[tid + off]; }
        __syncthreads();
    }
    if (tid == 0) {
        double mean = sh_s[0] / 102400.0;
        double var  = sh_ss[0] / 102400.0 - mean * mean;
        float sc = __ldg(gamma + c) * rsqrtf((float)var + 1e-5f);
        g_scale[rc] = sc;
        g_shift[rc] = __ldg(beta + c) - (float)mean * sc;
    }
}

// ------------------------- rconv: implicit GEMM, pre-activated input, N=32, K=320(288) -------------------------
__global__ void __launch_bounds__(128) rconv_mma(const float* __restrict__ bias) {
    __shared__ uint32_t smem_u[10240];           // 40960 B
    char* smem = (char*)smem_u;
    uint32_t sb = smem_u32(smem);
    int tid = threadIdx.x, wid = tid >> 5, lane = tid & 31;

    int p  = blockIdx.x * 128 + tid;
    int xo = p % 160, yo = (p / 160) % 160, b = p / 25600;
    int lx = xo % 40, ly = yo % 40;
    const uint32_t* ain = g_actHL + b * 819200 + yo * 160 + xo;

    // 9-bit validity mask over taps t = ty*3+tx
    int ry = ((ly > 0) ? 1 : 0) | 2 | ((ly < 39) ? 4 : 0);
    int cx = ((lx > 0) ? 1 : 0) | 2 | ((lx < 39) ? 4 : 0);
    int mask = 0;
#pragma unroll
    for (int ty = 0; ty < 3; ty++)
#pragma unroll
        for (int tx = 0; tx < 3; tx++)
            if (((ry >> ty) & 1) && ((cx >> tx) & 1)) mask |= 1 << (ty*3 + tx);

    float acc[32];
#pragma unroll
    for (int i = 0; i < 32; i++) acc[i] = 0.f;

    for (int c = 0; c < 5; c++) {
        int k0 = c * 64;
#pragma unroll 8
        for (int i = 0; i < 32; i++) {
            int k  = k0 + 2 * i;
            int t  = k >> 5;
            int ic = k & 31;          // even
            uint32_t v0 = 0u, v1 = 0u;
            if (t < 9 && ((mask >> t) & 1)) {
                int ty = t / 3;
                int dd = (ty - 1) * 160 + (t - ty * 3 - 1);
                const uint32_t* q = ain + ic * 25600 + dd;
                v0 = __ldg(q);
                v1 = __ldg(q + 25600);
            }
            uint32_t off = sw128((uint32_t)(tid * 128 + i * 4));
            *(uint32_t*)(smem + OFF_AHI + off) = __byte_perm(v0, v1, 0x5410);
            *(uint32_t*)(smem + OFF_ALO + off) = __byte_perm(v0, v1, 0x7632);
        }
#pragma unroll
        for (int e = tid; e < 1024; e += 128) {
            int oc = e >> 5, i = e & 31;
            uint2 w2 = __ldg((const uint2*)(g_wrHL + oc*320 + k0 + 2*i));
            uint32_t off = sw128((uint32_t)(oc * 128 + i * 4));
            *(uint32_t*)(smem + OFF_BHI + off) = __byte_perm(w2.x, w2.y, 0x5410);
            *(uint32_t*)(smem + OFF_BLO + off) = __byte_perm(w2.x, w2.y, 0x7632);
        }
        __syncthreads();
        mma_chunk_n32(sb, wid, lane, acc);
        __syncthreads();
    }
    float* op = g_bufB + (b * 32 * 160 + yo) * 160 + xo;
    epilogue_n32(smem, wid, lane, tid, acc, op, bias);
}

// ------------------------- 2x2 maxpool, 160->80, fused split -------------------------
__global__ void pool_kernel() {
    int t = blockIdx.x * blockDim.x + threadIdx.x;
    if (t >= BATCH * 32 * 80 * 80) return;
    int xx = t % 80;
    int y  = (t / 80) % 80;
    int bc = t / 6400;
    const float* p = g_bufB + (bc * 160 + 2 * y) * 160 + 2 * xx;
    g_poolHL[t] = packHL(fmaxf(fmaxf(p[0], p[1]), fmaxf(p[160], p[161])));
}

// ------------------------- conv4: implicit GEMM, N=16, K=2048 -------------------------
#define CONV4_M (BATCH * 73 * 73)
#define C4_BHI 32768
#define C4_BLO 34816
__global__ void __launch_bounds__(128) conv4_mma(const float* __restrict__ bias) {
    __shared__ uint32_t smem_u[9216];            // 36864 B
    char* smem = (char*)smem_u;
    uint32_t sb = smem_u32(smem);
    int tid = threadIdx.x, wid = tid >> 5, lane = tid & 31;

    int p  = blockIdx.x * 128 + tid;
    bool pv = p < CONV4_M;
    int pp = pv ? p : 0;
    int xo = pp % 73, yo = (pp / 73) % 73, b = pp / 5329;
    const uint32_t* pin = g_poolHL + b * 204800 + yo * 80 + xo;

    float acc[16];
#pragma unroll
    for (int i = 0; i < 16; i++) acc[i] = 0.f;

    for (int c = 0; c < 32; c++) {
        int k0 = c * 64;
#pragma unroll 8
        for (int i = 0; i < 32; i++) {
            int k  = k0 + 2 * i;
            int ic = k >> 6;
            int r  = k & 63;
            int ky = r >> 3, kx = r & 7;   // kx even
            uint32_t v0 = 0u, v1 = 0u;
            if (pv) {
                const uint32_t* q = pin + ic * 6400 + ky * 80 + kx;
                v0 = __ldg(q);
                v1 = __ldg(q + 1);
            }
            uint32_t off = sw128((uint32_t)(tid * 128 + i * 4));
            *(uint32_t*)(smem + OFF_AHI + off) = __byte_perm(v0, v1, 0x5410);
            *(uint32_t*)(smem + OFF_ALO + off) = __byte_perm(v0, v1, 0x7632);
        }
#pragma unroll
        for (int e = tid; e < 512; e += 128) {
            int oc = e >> 5, i = e & 31;
            uint2 w2 = __ldg((const uint2*)(g_w4HL + oc*2048 + k0 + 2*i));
            uint32_t off = sw128((uint32_t)(oc * 128 + i * 4));
            *(uint32_t*)(smem + C4_BHI + off) = __byte_perm(w2.x, w2.y, 0x5410);
            *(uint32_t*)(smem + C4_BLO + off) = __byte_perm(w2.x, w2.y, 0x7632);
        }
        __syncthreads();
#pragma unroll
        for (int ks = 0; ks < 4; ks++) {
            uint32_t a_hi[8], a_lo[8], b_hi[4], b_lo[4];
            uint32_t abyte = (uint32_t)((wid*32 + (lane & 15))*128 + (ks*16 + ((lane >> 4) << 3))*2);
            ldsm4(&a_hi[0], sb + OFF_AHI + sw128(abyte));
            ldsm4(&a_hi[4], sb + OFF_AHI + sw128(abyte) + 2048);
            ldsm4(&a_lo[0], sb + OFF_ALO + sw128(abyte));
            ldsm4(&a_lo[4], sb + OFF_ALO + sw128(abyte) + 2048);
            uint32_t bbyte = (uint32_t)(((((lane >> 4) << 3) + (lane & 7))*128) + (ks*16 + (lane & 8))*2);
            ldsm4(b_hi, sb + C4_BHI + sw128(bbyte));
            ldsm4(b_lo, sb + C4_BLO + sw128(bbyte));
#pragma unroll
            for (int mt = 0; mt < 2; mt++) {
#pragma unroll
                for (int nt = 0; nt < 2; nt++) {
                    float* cc = acc + (mt*2 + nt)*4;
                    const uint32_t* A  = a_hi + mt*4;
                    const uint32_t* Al = a_lo + mt*4;
                    uint32_t bh0 = b_hi[nt*2], bh1 = b_hi[nt*2+1];
                    uint32_t bl0 = b_lo[nt*2], bl1 = b_lo[nt*2+1];
                    mma_bf16(cc, A[0],A[1],A[2],A[3],   bh0, bh1);
                    mma_bf16(cc, Al[0],Al[1],Al[2],Al[3], bh0, bh1);
                    mma_bf16(cc, A[0],A[1],A[2],A[3],   bl0, bl1);
                }
            }
        }
        __syncthreads();
    }
    // stage + store
    float* stg = (float*)smem;
#pragma unroll
    for (int mt = 0; mt < 2; mt++)
#pragma unroll
        for (int nt = 0; nt < 2; nt++)
#pragma unroll
            for (int r = 0; r < 4; r++) {
                int row = wid*32 + mt*16 + (lane >> 2) + ((r >> 1) << 3);
                int col = nt*8 + ((lane & 3) << 1) + (r & 1);
                stg[row*17 + col] = acc[(mt*2 + nt)*4 + r];
            }
    __syncthreads();
    if (pv) {
        float* op = g_c4 + (b * 16 * 73 + yo) * 73 + xo;
#pragma unroll
        for (int j = 0; j < 16; j++)
            op[j * 5329] = stg[tid*17 + j] + __ldg(bias + j);
    }
}

// ------------------------- weight transpose for remaining direct convs -------------------------
#define DEFINE_TRANS(NAME, OC, R, DST)                                        \
__global__ void NAME(const float* __restrict__ w) {                           \
    int e = blockIdx.x * blockDim.x + threadIdx.x;                            \
    if (e < (OC)*(R)) {                                                       \
        int oc = e / (R);                                                     \
        int r  = e - oc * (R);                                                \
        DST[r*(OC) + oc] = w[e];                                              \
    }                                                                         \
}
DEFINE_TRANS(t_w5,  16, 1024, g_wT5)
DEFINE_TRANS(t_w6,  16,  576, g_wT6)
DEFINE_TRANS(t_w7,  16,  400, g_wT7)
DEFINE_TRANS(t_w8,  16,  144, g_wT8)
DEFINE_TRANS(t_wfc, 512, 1024, g_wTfc)

// ------------------------- generic OC=16 direct conv, 2 pixels/thread -------------------------
#define DEFINE_CONV16(NAME, IC, K, S, IH, IW, OH, OW, INBUF, WTBUF, OUTBUF)          \
__global__ void __launch_bounds__(128) NAME(const float* __restrict__ bias) {        \
    const int XP  = ((OW) + 1) / 2;                                                  \
    const int OFF = (OW) - XP;                                                       \
    int t = blockIdx.x * 128 + threadIdx.x;                                          \
    if (t >= BATCH * (OH) * XP) return;                                              \
    int xo = t % XP;                                                                 \
    int yo = (t / XP) % (OH);                                                        \
    int b  = t / (XP * (OH));                                                        \
    float a0[16], a1[16];                                                            \
    _Pragma("unroll")                                                                \
    for (int j = 0; j < 16; j++) { float bv = __ldg(bias + j); a0[j] = bv; a1[j] = bv; } \
    for (int ic = 0; ic < (IC); ic++) {                                              \
        const float* inp = INBUF + ((b*(IC) + ic)*(IH) + yo*(S))*(IW) + xo*(S);      \
        _Pragma("unroll 1")                                                          \
        for (int ky = 0; ky < (K); ky++) {                                           \
            const float* row = inp + ky*(IW);                                        \
            const float4* wrow = (const float4*)(WTBUF + (ic*(K)*(K) + ky*(K))*16);  \
            _Pragma("unroll")                                                        \
            for (int kx = 0; kx < (K); kx++) {                                       \
                float v0 = __ldg(row + kx);                                          \
                float v1 = __ldg(row + OFF*(S) + kx);                                \
                _Pragma("unroll")                                                    \
                for (int j = 0; j < 4; j++) {                                        \
                    float4 w4 = __ldg(wrow + kx*4 + j);                              \
                    a0[4*j+0] = fmaf(v0, w4.x, a0[4*j+0]); a1[4*j+0] = fmaf(v1, w4.x, a1[4*j+0]); \
                    a0[4*j+1] = fmaf(v0, w4.y, a0[4*j+1]); a1[4*j+1] = fmaf(v1, w4.y, a1[4*j+1]); \
                    a0[4*j+2] = fmaf(v0, w4.z, a0[4*j+2]); a1[4*j+2] = fmaf(v1, w4.z, a1[4*j+2]); \
                    a0[4*j+3] = fmaf(v0, w4.w, a0[4*j+3]); a1[4*j+3] = fmaf(v1, w4.w, a1[4*j+3]); \
                }                                                                    \
            }                                                                        \
        }                                                                            \
    }                                                                                \
    float* op = OUTBUF + (b*16*(OH) + yo)*(OW) + xo;                                 \
    _Pragma("unroll")                                                                \
    for (int j = 0; j < 16; j++) {                                                   \
        op[j*(OH)*(OW)]       = a0[j];                                               \
        op[j*(OH)*(OW) + OFF] = a1[j];                                               \
    }                                                                                \
}

DEFINE_CONV16(conv5_kernel, 16, 8, 2, 73, 73, 33, 33, g_c4, g_wT5, g_c5)
DEFINE_CONV16(conv6_kernel, 16, 6, 1, 33, 33, 28, 28, g_c5, g_wT6, g_c6)
DEFINE_CONV16(conv7_kernel, 16, 5, 1, 28, 28, 24, 24, g_c6, g_wT7, g_c7)
DEFINE_CONV16(conv8_kernel, 16, 3, 3, 24, 24,  8,  8, g_c7, g_wT8, g_c8)

// ------------------------- FC -------------------------
__global__ void fc_kernel(const float* __restrict__ bias, float* __restrict__ out) {
    __shared__ float sm[1024];
    int b = blockIdx.x;
    int o = threadIdx.x;
    sm[o]       = g_c8[b * 1024 + o];
    sm[o + 512] = g_c8[b * 1024 + o + 512];
    __syncthreads();
    float acc = __ldg(bias + o);
#pragma unroll 4
    for (int k = 0; k < 1024; k++)
        acc = fmaf(sm[k], g_wTfc[k * 512 + o], acc);
    out[b * 512 + o] = acc;
}

// ------------------------- launch -------------------------
static inline int gridFor(long n, int bs) { return (int)((n + bs - 1) / bs); }

extern "C" void kernel_launch(void* const* d_in, const int* in_sizes, int n_in,
                              void* d_out, int out_size) {
    const float* x        = (const float*)d_in[0];
    const float* conv1_w  = (const float*)d_in[1];
    const float* conv1_b  = (const float*)d_in[2];
    const float* bn_gamma = (const float*)d_in[3];
    const float* bn_beta  = (const float*)d_in[4];
    const float* prelu_a  = (const float*)d_in[5];
    const float* rconv_w  = (const float*)d_in[6];
    const float* rconv_b  = (const float*)d_in[7];
    const float* conv4_w  = (const float*)d_in[8];
    const float* conv4_b  = (const float*)d_in[9];
    const float* conv5_b  = (const float*)d_in[11];
    const float* conv6_b  = (const float*)d_in[13];
    const float* conv7_b  = (const float*)d_in[15];
    const float* conv8_b  = (const float*)d_in[17];
    const float* fc_b     = (const float*)d_in[19];
    float* out = (float*)d_out;

    // pre-passes
    split_x<<<gridFor((long)BATCH*3*170*170, 256), 256>>>(x);
    t_w1hl<<<gridFor(32*384, 256), 256>>>(conv1_w);
    t_wrhl<<<gridFor(32*320, 256), 256>>>(rconv_w);
    t_w4hl<<<gridFor(16*2048, 256), 256>>>(conv4_w);
    t_w5 <<<gridFor(16*1024, 256), 256>>>((const float*)d_in[10]);
    t_w6 <<<gridFor(16*576,  256), 256>>>((const float*)d_in[12]);
    t_w7 <<<gridFor(16*400,  256), 256>>>((const float*)d_in[14]);
    t_w8 <<<gridFor(16*144,  256), 256>>>((const float*)d_in[16]);
    t_wfc<<<gridFor(512*1024,256), 256>>>((const float*)d_in[18]);

    conv1_mma<<<12800, 128>>>(conv1_b);
    stats_kernel<<<512, 256>>>(bn_gamma, bn_beta);
    act_kernel<<<gridFor((long)BATCH*32*160*160, 256), 256>>>(prelu_a);
    rconv_mma<<<12800, 128>>>(rconv_b);
    pool_kernel<<<gridFor((long)BATCH*32*80*80, 256), 256>>>();

    conv4_mma<<<gridFor(CONV4_M, 128), 128>>>(conv4_b);
    conv5_kernel<<<gridFor((long)BATCH*33*17, 128), 128>>>(conv5_b);
    conv6_kernel<<<gridFor((long)BATCH*28*14, 128), 128>>>(conv6_b);
    conv7_kernel<<<gridFor((long)BATCH*24*12, 128), 128>>>(conv7_b);
    conv8_kernel<<<gridFor((long)BATCH*8*4,   128), 128>>>(conv8_b);

    fc_kernel<<<BATCH, 512>>>(fc_b, out);
}